// round 1
// baseline (speedup 1.0000x reference)
#include <cuda_runtime.h>
#include <cstdint>

#define Bdim 2
#define Hdim 16
#define Sdim 2048
#define Ddim 128
#define BHdim (Bdim * Hdim)

typedef unsigned long long u64;

__device__ __forceinline__ u64 pack2(float lo, float hi) {
    u64 r;
    asm("mov.b64 %0, {%1, %2};" : "=l"(r) : "f"(lo), "f"(hi));
    return r;
}
__device__ __forceinline__ void unpack2(u64 v, float& lo, float& hi) {
    asm("mov.b64 {%0, %1}, %2;" : "=f"(lo), "=f"(hi) : "l"(v));
}
__device__ __forceinline__ u64 fma2(u64 a, u64 b, u64 c) {
    u64 d;
    asm("fma.rn.f32x2 %0, %1, %2, %3;" : "=l"(d) : "l"(a), "l"(b), "l"(c));
    return d;
}

// ---------------------------------------------------------------------------
// Kernel 1: scores = scale * Q @ K^T   (per head: [2048,128] x [2048,128]^T)
// Block tile 128x128, depth chunk 16, 256 threads, 8x8 micro-tile per thread.
// ---------------------------------------------------------------------------
__global__ __launch_bounds__(256, 2)
void qk_kernel(const float* __restrict__ Q, const float* __restrict__ Km,
               float* __restrict__ W)
{
    __shared__ float As[16][128];   // Q^T chunk: As[t][m] = Q[q0+m][kk+t]
    __shared__ float Bs[16][128];   // K^T chunk: Bs[t][n] = K[k0+n][kk+t]

    const int bh = blockIdx.z;
    const int q0 = blockIdx.y * 128;
    const int k0 = blockIdx.x * 128;
    const float* Qh = Q  + (size_t)bh * Sdim * Ddim;
    const float* Kh = Km + (size_t)bh * Sdim * Ddim;
    float*       Wh = W  + (size_t)bh * Sdim * Sdim;

    const int tid  = threadIdx.x;
    const int lrow = tid >> 1;          // 0..127
    const int lt   = (tid & 1) * 8;     // 0 or 8
    const int tm   = tid >> 4;          // 0..15
    const int tn   = tid & 15;          // 0..15

    u64 acc[8][4];
#pragma unroll
    for (int i = 0; i < 8; i++)
#pragma unroll
        for (int j = 0; j < 4; j++) acc[i][j] = 0ULL;

    const float* qptr = Qh + (size_t)(q0 + lrow) * Ddim + lt;
    const float* kptr = Kh + (size_t)(k0 + lrow) * Ddim + lt;

    for (int kk = 0; kk < Ddim; kk += 16) {
        float4 qa = *(const float4*)(qptr + kk);
        float4 qb = *(const float4*)(qptr + kk + 4);
        float4 ka = *(const float4*)(kptr + kk);
        float4 kb = *(const float4*)(kptr + kk + 4);

        As[lt + 0][lrow] = qa.x; As[lt + 1][lrow] = qa.y;
        As[lt + 2][lrow] = qa.z; As[lt + 3][lrow] = qa.w;
        As[lt + 4][lrow] = qb.x; As[lt + 5][lrow] = qb.y;
        As[lt + 6][lrow] = qb.z; As[lt + 7][lrow] = qb.w;

        Bs[lt + 0][lrow] = ka.x; Bs[lt + 1][lrow] = ka.y;
        Bs[lt + 2][lrow] = ka.z; Bs[lt + 3][lrow] = ka.w;
        Bs[lt + 4][lrow] = kb.x; Bs[lt + 5][lrow] = kb.y;
        Bs[lt + 6][lrow] = kb.z; Bs[lt + 7][lrow] = kb.w;

        __syncthreads();

#pragma unroll
        for (int t = 0; t < 16; t++) {
            float4 a0 = *(const float4*)&As[t][tm * 8];
            float4 a1 = *(const float4*)&As[t][tm * 8 + 4];
            float4 b0 = *(const float4*)&Bs[t][tn * 8];
            float4 b1 = *(const float4*)&Bs[t][tn * 8 + 4];
            float av[8] = {a0.x, a0.y, a0.z, a0.w, a1.x, a1.y, a1.z, a1.w};
            u64 bp[4] = {pack2(b0.x, b0.y), pack2(b0.z, b0.w),
                         pack2(b1.x, b1.y), pack2(b1.z, b1.w)};
#pragma unroll
            for (int i = 0; i < 8; i++) {
                u64 ad = pack2(av[i], av[i]);
#pragma unroll
                for (int j = 0; j < 4; j++) acc[i][j] = fma2(ad, bp[j], acc[i][j]);
            }
        }
        __syncthreads();
    }

    const float scale = 0.08838834764831843f;  // 1/sqrt(128)
#pragma unroll
    for (int i = 0; i < 8; i++) {
        float c[8];
#pragma unroll
        for (int j = 0; j < 4; j++) unpack2(acc[i][j], c[2 * j], c[2 * j + 1]);
#pragma unroll
        for (int j = 0; j < 8; j++) c[j] *= scale;
        float4* dst = (float4*)(Wh + (size_t)(q0 + tm * 8 + i) * Sdim + k0 + tn * 8);
        dst[0] = make_float4(c[0], c[1], c[2], c[3]);
        dst[1] = make_float4(c[4], c[5], c[6], c[7]);
    }
}

// ---------------------------------------------------------------------------
// Kernel 2: in-place row softmax over the weights region. One block per row.
// ---------------------------------------------------------------------------
__global__ __launch_bounds__(256)
void softmax_kernel(float* __restrict__ W)
{
    float* p = W + (size_t)blockIdx.x * Sdim;
    const int tid = threadIdx.x;
    const int lane = tid & 31;
    const int warp = tid >> 5;

    float4 v0 = *(const float4*)(p + tid * 8);
    float4 v1 = *(const float4*)(p + tid * 8 + 4);
    float x[8] = {v0.x, v0.y, v0.z, v0.w, v1.x, v1.y, v1.z, v1.w};

    __shared__ float smax[8];
    __shared__ float ssum[8];

    float m = x[0];
#pragma unroll
    for (int j = 1; j < 8; j++) m = fmaxf(m, x[j]);
#pragma unroll
    for (int o = 16; o > 0; o >>= 1) m = fmaxf(m, __shfl_xor_sync(0xffffffffu, m, o));
    if (lane == 0) smax[warp] = m;
    __syncthreads();
    float bm = smax[0];
#pragma unroll
    for (int w = 1; w < 8; w++) bm = fmaxf(bm, smax[w]);

    float s = 0.f;
#pragma unroll
    for (int j = 0; j < 8; j++) { x[j] = __expf(x[j] - bm); s += x[j]; }
#pragma unroll
    for (int o = 16; o > 0; o >>= 1) s += __shfl_xor_sync(0xffffffffu, s, o);
    if (lane == 0) ssum[warp] = s;
    __syncthreads();
    float bs = 0.f;
#pragma unroll
    for (int w = 0; w < 8; w++) bs += ssum[w];

    const float inv = 1.f / bs;
#pragma unroll
    for (int j = 0; j < 8; j++) x[j] *= inv;
    *(float4*)(p + tid * 8)     = make_float4(x[0], x[1], x[2], x[3]);
    *(float4*)(p + tid * 8 + 4) = make_float4(x[4], x[5], x[6], x[7]);
}

// ---------------------------------------------------------------------------
// Kernel 3: output = P @ V   (per head: [2048,2048] x [2048,128])
// Block tile 128x128 (BN covers full D), depth chunk 16, 256 threads.
// ---------------------------------------------------------------------------
__global__ __launch_bounds__(256, 2)
void pv_kernel(const float* __restrict__ W, const float* __restrict__ V,
               float* __restrict__ O)
{
    __shared__ float As[16][128];   // As[t][m] = W[q0+m][kk+t]
    __shared__ float Bs[16][128];   // Bs[t][n] = V[kk+t][n]

    const int bh = blockIdx.z;
    const int q0 = blockIdx.y * 128;
    const float* Wh = W + (size_t)bh * Sdim * Sdim;
    const float* Vh = V + (size_t)bh * Sdim * Ddim;
    float*       Oh = O + (size_t)bh * Sdim * Ddim;

    const int tid  = threadIdx.x;
    const int lrow = tid >> 1;          // 0..127 (W row within tile)
    const int lt   = (tid & 1) * 8;     // 0 or 8 (W depth offset)
    const int vrow = tid >> 4;          // 0..15  (V row within chunk)
    const int vcol = (tid & 15) * 8;    // 0..120 (V col)
    const int tm   = tid >> 4;
    const int tn   = tid & 15;

    u64 acc[8][4];
#pragma unroll
    for (int i = 0; i < 8; i++)
#pragma unroll
        for (int j = 0; j < 4; j++) acc[i][j] = 0ULL;

    const float* wptr = Wh + (size_t)(q0 + lrow) * Sdim + lt;

    for (int kk = 0; kk < Sdim; kk += 16) {
        float4 wa = *(const float4*)(wptr + kk);
        float4 wb = *(const float4*)(wptr + kk + 4);
        float4 va = *(const float4*)(Vh + (size_t)(kk + vrow) * Ddim + vcol);
        float4 vb = *(const float4*)(Vh + (size_t)(kk + vrow) * Ddim + vcol + 4);

        As[lt + 0][lrow] = wa.x; As[lt + 1][lrow] = wa.y;
        As[lt + 2][lrow] = wa.z; As[lt + 3][lrow] = wa.w;
        As[lt + 4][lrow] = wb.x; As[lt + 5][lrow] = wb.y;
        As[lt + 6][lrow] = wb.z; As[lt + 7][lrow] = wb.w;

        *(float4*)&Bs[vrow][vcol]     = va;
        *(float4*)&Bs[vrow][vcol + 4] = vb;

        __syncthreads();

#pragma unroll
        for (int t = 0; t < 16; t++) {
            float4 a0 = *(const float4*)&As[t][tm * 8];
            float4 a1 = *(const float4*)&As[t][tm * 8 + 4];
            float4 b0 = *(const float4*)&Bs[t][tn * 8];
            float4 b1 = *(const float4*)&Bs[t][tn * 8 + 4];
            float av[8] = {a0.x, a0.y, a0.z, a0.w, a1.x, a1.y, a1.z, a1.w};
            u64 bp[4] = {pack2(b0.x, b0.y), pack2(b0.z, b0.w),
                         pack2(b1.x, b1.y), pack2(b1.z, b1.w)};
#pragma unroll
            for (int i = 0; i < 8; i++) {
                u64 ad = pack2(av[i], av[i]);
#pragma unroll
                for (int j = 0; j < 4; j++) acc[i][j] = fma2(ad, bp[j], acc[i][j]);
            }
        }
        __syncthreads();
    }

#pragma unroll
    for (int i = 0; i < 8; i++) {
        float c[8];
#pragma unroll
        for (int j = 0; j < 4; j++) unpack2(acc[i][j], c[2 * j], c[2 * j + 1]);
        float4* dst = (float4*)(Oh + (size_t)(q0 + tm * 8 + i) * Ddim + tn * 8);
        dst[0] = make_float4(c[0], c[1], c[2], c[3]);
        dst[1] = make_float4(c[4], c[5], c[6], c[7]);
    }
}

// ---------------------------------------------------------------------------
// Launch: d_out = [output (B*H*S*D floats) | attn_weights (B*H*S*S floats)]
// ---------------------------------------------------------------------------
extern "C" void kernel_launch(void* const* d_in, const int* in_sizes, int n_in,
                              void* d_out, int out_size)
{
    const float* Q = (const float*)d_in[0];
    const float* K = (const float*)d_in[1];
    const float* V = (const float*)d_in[2];
    float* out = (float*)d_out;
    float* Wt  = out + (size_t)Bdim * Hdim * Sdim * Ddim;  // weights region

    dim3 g1(Sdim / 128, Sdim / 128, BHdim);
    qk_kernel<<<g1, 256>>>(Q, K, Wt);

    softmax_kernel<<<dim3(BHdim * Sdim), 256>>>(Wt);

    dim3 g3(1, Sdim / 128, BHdim);
    pv_kernel<<<g3, 256>>>(Wt, V, out);
}

// round 2
// speedup vs baseline: 1.0012x; 1.0012x over previous
#include <cuda_runtime.h>
#include <cstdint>

#define Bdim 2
#define Hdim 16
#define Sdim 2048
#define Ddim 128
#define BHdim (Bdim * Hdim)

typedef unsigned long long u64;

__device__ __forceinline__ u64 pack2(float lo, float hi) {
    u64 r;
    asm("mov.b64 %0, {%1, %2};" : "=l"(r) : "f"(lo), "f"(hi));
    return r;
}
__device__ __forceinline__ void unpack2(u64 v, float& lo, float& hi) {
    asm("mov.b64 {%0, %1}, %2;" : "=f"(lo), "=f"(hi) : "l"(v));
}
__device__ __forceinline__ u64 fma2(u64 a, u64 b, u64 c) {
    u64 d;
    asm("fma.rn.f32x2 %0, %1, %2, %3;" : "=l"(d) : "l"(a), "l"(b), "l"(c));
    return d;
}

// ---------------------------------------------------------------------------
// Kernel 1: scores = scale * Q @ K^T   (per head: [2048,128] x [2048,128]^T)
// Block tile 128x128, depth chunk 16, 256 threads, 8x8 micro-tile per thread.
// ---------------------------------------------------------------------------
__global__ __launch_bounds__(256, 2)
void qk_kernel(const float* __restrict__ Q, const float* __restrict__ Km,
               float* __restrict__ W)
{
    __shared__ float As[16][128];   // Q^T chunk: As[t][m] = Q[q0+m][kk+t]
    __shared__ float Bs[16][128];   // K^T chunk: Bs[t][n] = K[k0+n][kk+t]

    const int bh = blockIdx.z;
    const int q0 = blockIdx.y * 128;
    const int k0 = blockIdx.x * 128;
    const float* Qh = Q  + (size_t)bh * Sdim * Ddim;
    const float* Kh = Km + (size_t)bh * Sdim * Ddim;
    float*       Wh = W  + (size_t)bh * Sdim * Sdim;

    const int tid  = threadIdx.x;
    const int lrow = tid >> 1;          // 0..127
    const int lt   = (tid & 1) * 8;     // 0 or 8
    const int tm   = tid >> 4;          // 0..15
    const int tn   = tid & 15;          // 0..15

    u64 acc[8][4];
#pragma unroll
    for (int i = 0; i < 8; i++)
#pragma unroll
        for (int j = 0; j < 4; j++) acc[i][j] = 0ULL;

    const float* qptr = Qh + (size_t)(q0 + lrow) * Ddim + lt;
    const float* kptr = Kh + (size_t)(k0 + lrow) * Ddim + lt;

    for (int kk = 0; kk < Ddim; kk += 16) {
        float4 qa = *(const float4*)(qptr + kk);
        float4 qb = *(const float4*)(qptr + kk + 4);
        float4 ka = *(const float4*)(kptr + kk);
        float4 kb = *(const float4*)(kptr + kk + 4);

        As[lt + 0][lrow] = qa.x; As[lt + 1][lrow] = qa.y;
        As[lt + 2][lrow] = qa.z; As[lt + 3][lrow] = qa.w;
        As[lt + 4][lrow] = qb.x; As[lt + 5][lrow] = qb.y;
        As[lt + 6][lrow] = qb.z; As[lt + 7][lrow] = qb.w;

        Bs[lt + 0][lrow] = ka.x; Bs[lt + 1][lrow] = ka.y;
        Bs[lt + 2][lrow] = ka.z; Bs[lt + 3][lrow] = ka.w;
        Bs[lt + 4][lrow] = kb.x; Bs[lt + 5][lrow] = kb.y;
        Bs[lt + 6][lrow] = kb.z; Bs[lt + 7][lrow] = kb.w;

        __syncthreads();

#pragma unroll
        for (int t = 0; t < 16; t++) {
            float4 a0 = *(const float4*)&As[t][tm * 8];
            float4 a1 = *(const float4*)&As[t][tm * 8 + 4];
            float4 b0 = *(const float4*)&Bs[t][tn * 8];
            float4 b1 = *(const float4*)&Bs[t][tn * 8 + 4];
            float av[8] = {a0.x, a0.y, a0.z, a0.w, a1.x, a1.y, a1.z, a1.w};
            u64 bp[4] = {pack2(b0.x, b0.y), pack2(b0.z, b0.w),
                         pack2(b1.x, b1.y), pack2(b1.z, b1.w)};
#pragma unroll
            for (int i = 0; i < 8; i++) {
                u64 ad = pack2(av[i], av[i]);
#pragma unroll
                for (int j = 0; j < 4; j++) acc[i][j] = fma2(ad, bp[j], acc[i][j]);
            }
        }
        __syncthreads();
    }

    const float scale = 0.08838834764831843f;  // 1/sqrt(128)
#pragma unroll
    for (int i = 0; i < 8; i++) {
        float c[8];
#pragma unroll
        for (int j = 0; j < 4; j++) unpack2(acc[i][j], c[2 * j], c[2 * j + 1]);
#pragma unroll
        for (int j = 0; j < 8; j++) c[j] *= scale;
        float4* dst = (float4*)(Wh + (size_t)(q0 + tm * 8 + i) * Sdim + k0 + tn * 8);
        dst[0] = make_float4(c[0], c[1], c[2], c[3]);
        dst[1] = make_float4(c[4], c[5], c[6], c[7]);
    }
}

// ---------------------------------------------------------------------------
// Kernel 2: in-place row softmax over the weights region. One block per row.
// ---------------------------------------------------------------------------
__global__ __launch_bounds__(256)
void softmax_kernel(float* __restrict__ W)
{
    float* p = W + (size_t)blockIdx.x * Sdim;
    const int tid = threadIdx.x;
    const int lane = tid & 31;
    const int warp = tid >> 5;

    float4 v0 = *(const float4*)(p + tid * 8);
    float4 v1 = *(const float4*)(p + tid * 8 + 4);
    float x[8] = {v0.x, v0.y, v0.z, v0.w, v1.x, v1.y, v1.z, v1.w};

    __shared__ float smax[8];
    __shared__ float ssum[8];

    float m = x[0];
#pragma unroll
    for (int j = 1; j < 8; j++) m = fmaxf(m, x[j]);
#pragma unroll
    for (int o = 16; o > 0; o >>= 1) m = fmaxf(m, __shfl_xor_sync(0xffffffffu, m, o));
    if (lane == 0) smax[warp] = m;
    __syncthreads();
    float bm = smax[0];
#pragma unroll
    for (int w = 1; w < 8; w++) bm = fmaxf(bm, smax[w]);

    float s = 0.f;
#pragma unroll
    for (int j = 0; j < 8; j++) { x[j] = __expf(x[j] - bm); s += x[j]; }
#pragma unroll
    for (int o = 16; o > 0; o >>= 1) s += __shfl_xor_sync(0xffffffffu, s, o);
    if (lane == 0) ssum[warp] = s;
    __syncthreads();
    float bs = 0.f;
#pragma unroll
    for (int w = 0; w < 8; w++) bs += ssum[w];

    const float inv = 1.f / bs;
#pragma unroll
    for (int j = 0; j < 8; j++) x[j] *= inv;
    *(float4*)(p + tid * 8)     = make_float4(x[0], x[1], x[2], x[3]);
    *(float4*)(p + tid * 8 + 4) = make_float4(x[4], x[5], x[6], x[7]);
}

// ---------------------------------------------------------------------------
// Kernel 3: output = P @ V   (per head: [2048,2048] x [2048,128])
// Block tile 128x128 (BN covers full D), depth chunk 16, 256 threads.
// ---------------------------------------------------------------------------
__global__ __launch_bounds__(256, 2)
void pv_kernel(const float* __restrict__ W, const float* __restrict__ V,
               float* __restrict__ O)
{
    __shared__ float As[16][128];   // As[t][m] = W[q0+m][kk+t]
    __shared__ float Bs[16][128];   // Bs[t][n] = V[kk+t][n]

    const int bh = blockIdx.z;
    const int q0 = blockIdx.y * 128;
    const float* Wh = W + (size_t)bh * Sdim * Sdim;
    const float* Vh = V + (size_t)bh * Sdim * Ddim;
    float*       Oh = O + (size_t)bh * Sdim * Ddim;

    const int tid  = threadIdx.x;
    const int lrow = tid >> 1;          // 0..127 (W row within tile)
    const int lt   = (tid & 1) * 8;     // 0 or 8 (W depth offset)
    const int vrow = tid >> 4;          // 0..15  (V row within chunk)
    const int vcol = (tid & 15) * 8;    // 0..120 (V col)
    const int tm   = tid >> 4;
    const int tn   = tid & 15;

    u64 acc[8][4];
#pragma unroll
    for (int i = 0; i < 8; i++)
#pragma unroll
        for (int j = 0; j < 4; j++) acc[i][j] = 0ULL;

    const float* wptr = Wh + (size_t)(q0 + lrow) * Sdim + lt;

    for (int kk = 0; kk < Sdim; kk += 16) {
        float4 wa = *(const float4*)(wptr + kk);
        float4 wb = *(const float4*)(wptr + kk + 4);
        float4 va = *(const float4*)(Vh + (size_t)(kk + vrow) * Ddim + vcol);
        float4 vb = *(const float4*)(Vh + (size_t)(kk + vrow) * Ddim + vcol + 4);

        As[lt + 0][lrow] = wa.x; As[lt + 1][lrow] = wa.y;
        As[lt + 2][lrow] = wa.z; As[lt + 3][lrow] = wa.w;
        As[lt + 4][lrow] = wb.x; As[lt + 5][lrow] = wb.y;
        As[lt + 6][lrow] = wb.z; As[lt + 7][lrow] = wb.w;

        *(float4*)&Bs[vrow][vcol]     = va;
        *(float4*)&Bs[vrow][vcol + 4] = vb;

        __syncthreads();

#pragma unroll
        for (int t = 0; t < 16; t++) {
            float4 a0 = *(const float4*)&As[t][tm * 8];
            float4 a1 = *(const float4*)&As[t][tm * 8 + 4];
            float4 b0 = *(const float4*)&Bs[t][tn * 8];
            float4 b1 = *(const float4*)&Bs[t][tn * 8 + 4];
            float av[8] = {a0.x, a0.y, a0.z, a0.w, a1.x, a1.y, a1.z, a1.w};
            u64 bp[4] = {pack2(b0.x, b0.y), pack2(b0.z, b0.w),
                         pack2(b1.x, b1.y), pack2(b1.z, b1.w)};
#pragma unroll
            for (int i = 0; i < 8; i++) {
                u64 ad = pack2(av[i], av[i]);
#pragma unroll
                for (int j = 0; j < 4; j++) acc[i][j] = fma2(ad, bp[j], acc[i][j]);
            }
        }
        __syncthreads();
    }

#pragma unroll
    for (int i = 0; i < 8; i++) {
        float c[8];
#pragma unroll
        for (int j = 0; j < 4; j++) unpack2(acc[i][j], c[2 * j], c[2 * j + 1]);
        float4* dst = (float4*)(Oh + (size_t)(q0 + tm * 8 + i) * Ddim + tn * 8);
        dst[0] = make_float4(c[0], c[1], c[2], c[3]);
        dst[1] = make_float4(c[4], c[5], c[6], c[7]);
    }
}

// ---------------------------------------------------------------------------
// Launch: d_out = [output (B*H*S*D floats) | attn_weights (B*H*S*S floats)]
// ---------------------------------------------------------------------------
extern "C" void kernel_launch(void* const* d_in, const int* in_sizes, int n_in,
                              void* d_out, int out_size)
{
    const float* Q = (const float*)d_in[0];
    const float* K = (const float*)d_in[1];
    const float* V = (const float*)d_in[2];
    float* out = (float*)d_out;
    float* Wt  = out + (size_t)Bdim * Hdim * Sdim * Ddim;  // weights region

    dim3 g1(Sdim / 128, Sdim / 128, BHdim);
    qk_kernel<<<g1, 256>>>(Q, K, Wt);

    softmax_kernel<<<dim3(BHdim * Sdim), 256>>>(Wt);

    dim3 g3(1, Sdim / 128, BHdim);
    pv_kernel<<<g3, 256>>>(Wt, V, out);
}

// round 4
// speedup vs baseline: 1.9735x; 1.9711x over previous
#include <cuda_runtime.h>
#include <cuda_bf16.h>
#include <cstdint>

#define Bdim 2
#define Hdim 16
#define Sdim 2048
#define Ddim 128
#define BHdim (Bdim * Hdim)
#define NELEM 8388608   // BH * S * D

__device__ __nv_bfloat16 g_Qhi[NELEM];
__device__ __nv_bfloat16 g_Qlo[NELEM];
__device__ __nv_bfloat16 g_Khi[NELEM];
__device__ __nv_bfloat16 g_Klo[NELEM];
__device__ __nv_bfloat16 g_Vthi[NELEM];   // transposed: [bh][d][s]
__device__ __nv_bfloat16 g_Vtlo[NELEM];

// ------------------- helpers -------------------
__device__ __forceinline__ void mma_bf16(float& d0, float& d1, float& d2, float& d3,
                                         uint32_t a0, uint32_t a1, uint32_t a2, uint32_t a3,
                                         uint32_t b0, uint32_t b1) {
    asm volatile(
        "mma.sync.aligned.m16n8k16.row.col.f32.bf16.bf16.f32 "
        "{%0,%1,%2,%3}, {%4,%5,%6,%7}, {%8,%9}, {%0,%1,%2,%3};"
        : "+f"(d0), "+f"(d1), "+f"(d2), "+f"(d3)
        : "r"(a0), "r"(a1), "r"(a2), "r"(a3), "r"(b0), "r"(b1));
}
__device__ __forceinline__ uint32_t ld32bf(const __nv_bfloat16* p) {
    return *reinterpret_cast<const uint32_t*>(p);
}
__device__ __forceinline__ void split2(float a, float b, uint32_t& hi, uint32_t& lo) {
    __nv_bfloat16 ha = __float2bfloat16(a), hb = __float2bfloat16(b);
    float ra = a - __bfloat162float(ha);
    float rb = b - __bfloat162float(hb);
    __nv_bfloat162 hp; hp.x = ha; hp.y = hb;
    __nv_bfloat162 lp = __floats2bfloat162_rn(ra, rb);
    hi = *reinterpret_cast<uint32_t*>(&hp);
    lo = *reinterpret_cast<uint32_t*>(&lp);
}

// ------------------- convert kernels -------------------
__global__ __launch_bounds__(256)
void conv_qk_kernel(const float* __restrict__ Q, const float* __restrict__ K)
{
    const size_t n4 = (size_t)NELEM / 4;
    size_t i = (size_t)blockIdx.x * 256 + threadIdx.x;
    const float sc = 0.08838834764831843f;  // 1/sqrt(128)
    float4 v; __nv_bfloat16 *hip, *lop; size_t idx;
    if (i < n4) {
        idx = i;
        v = ((const float4*)Q)[idx];
        v.x *= sc; v.y *= sc; v.z *= sc; v.w *= sc;
        hip = g_Qhi; lop = g_Qlo;
    } else {
        idx = i - n4;
        v = ((const float4*)K)[idx];
        hip = g_Khi; lop = g_Klo;
    }
    uint32_t h0, h1, l0, l1;
    split2(v.x, v.y, h0, l0);
    split2(v.z, v.w, h1, l1);
    ((uint2*)hip)[idx] = make_uint2(h0, h1);
    ((uint2*)lop)[idx] = make_uint2(l0, l1);
}

__global__ __launch_bounds__(256)
void conv_v_kernel(const float* __restrict__ V)
{
    __shared__ float tile[32][33];
    const int bh = blockIdx.z;
    const int s0 = blockIdx.x * 32;
    const int d0 = blockIdx.y * 32;
    const int tx = threadIdx.x, ty = threadIdx.y;
    const float* Vh = V + (size_t)bh * Sdim * Ddim;

    for (int i = ty; i < 32; i += 8)
        tile[i][tx] = Vh[(size_t)(s0 + i) * Ddim + d0 + tx];
    __syncthreads();

    const size_t base = (size_t)bh * Ddim * Sdim;
    for (int i = ty; i < 32; i += 8) {
        float x = tile[tx][i];   // V[s0+tx][d0+i]
        __nv_bfloat16 hb = __float2bfloat16(x);
        float r = x - __bfloat162float(hb);
        size_t o = base + (size_t)(d0 + i) * Sdim + s0 + tx;
        g_Vthi[o] = hb;
        g_Vtlo[o] = __float2bfloat16(r);
    }
}

// ------------------- QK HMMA kernel -------------------
// CTA: 128 q-rows x 128 k-cols, full K=128 depth resident in SMEM.
// 8 warps in 2(M)x4(N); warp tile 64x32 = 4x4 m16n8 frags.
#define LDA_QK 136
#define QK_SMEM (4 * 128 * LDA_QK * 2)   // 139264 B

__global__ __launch_bounds__(256, 1)
void qk_mma_kernel(float* __restrict__ W)
{
    extern __shared__ __nv_bfloat16 sm[];
    __nv_bfloat16* sQhi = sm;
    __nv_bfloat16* sQlo = sm + 128 * LDA_QK;
    __nv_bfloat16* sKhi = sm + 2 * 128 * LDA_QK;
    __nv_bfloat16* sKlo = sm + 3 * 128 * LDA_QK;

    const int tid = threadIdx.x;
    const int bh = blockIdx.z;
    const int q0 = blockIdx.y * 128;
    const int k0 = blockIdx.x * 128;

    const size_t qbase = (size_t)bh * Sdim * Ddim + (size_t)q0 * Ddim;
    const size_t kbase = (size_t)bh * Sdim * Ddim + (size_t)k0 * Ddim;

#pragma unroll
    for (int j = 0; j < 8; j++) {
        int f = j * 256 + tid;
        int row = f >> 4, c8 = (f & 15) * 8;
        size_t g = (size_t)row * Ddim + c8;
        int s = row * LDA_QK + c8;
        *(uint4*)&sQhi[s] = *(const uint4*)(g_Qhi + qbase + g);
        *(uint4*)&sQlo[s] = *(const uint4*)(g_Qlo + qbase + g);
        *(uint4*)&sKhi[s] = *(const uint4*)(g_Khi + kbase + g);
        *(uint4*)&sKlo[s] = *(const uint4*)(g_Klo + kbase + g);
    }
    __syncthreads();

    const int lane = tid & 31, wid = tid >> 5;
    const int wm = (wid >> 2) * 64, wn = (wid & 3) * 32;
    const int ar = lane >> 2, ac = (lane & 3) * 2;

    float acc[4][4][4];
#pragma unroll
    for (int mi = 0; mi < 4; mi++)
#pragma unroll
        for (int ni = 0; ni < 4; ni++)
#pragma unroll
            for (int r = 0; r < 4; r++) acc[mi][ni][r] = 0.f;

#pragma unroll
    for (int ks = 0; ks < 8; ks++) {
        const int kb = ks * 16;
        uint32_t ah[4][4], al[4][4], bhv[4][2], blv[4][2];
#pragma unroll
        for (int mi = 0; mi < 4; mi++) {
            const int r = wm + mi * 16 + ar;
            const __nv_bfloat16* ph = &sQhi[r * LDA_QK + kb + ac];
            const __nv_bfloat16* pl = &sQlo[r * LDA_QK + kb + ac];
            ah[mi][0] = ld32bf(ph);                  ah[mi][1] = ld32bf(ph + 8 * LDA_QK);
            ah[mi][2] = ld32bf(ph + 8);              ah[mi][3] = ld32bf(ph + 8 * LDA_QK + 8);
            al[mi][0] = ld32bf(pl);                  al[mi][1] = ld32bf(pl + 8 * LDA_QK);
            al[mi][2] = ld32bf(pl + 8);              al[mi][3] = ld32bf(pl + 8 * LDA_QK + 8);
        }
#pragma unroll
        for (int ni = 0; ni < 4; ni++) {
            const int n = wn + ni * 8 + ar;
            const __nv_bfloat16* ph = &sKhi[n * LDA_QK + kb + ac];
            const __nv_bfloat16* pl = &sKlo[n * LDA_QK + kb + ac];
            bhv[ni][0] = ld32bf(ph); bhv[ni][1] = ld32bf(ph + 8);
            blv[ni][0] = ld32bf(pl); blv[ni][1] = ld32bf(pl + 8);
        }
#pragma unroll
        for (int mi = 0; mi < 4; mi++)
#pragma unroll
            for (int ni = 0; ni < 4; ni++) {
                float* c = acc[mi][ni];
                mma_bf16(c[0], c[1], c[2], c[3], ah[mi][0], ah[mi][1], ah[mi][2], ah[mi][3], bhv[ni][0], bhv[ni][1]);
                mma_bf16(c[0], c[1], c[2], c[3], ah[mi][0], ah[mi][1], ah[mi][2], ah[mi][3], blv[ni][0], blv[ni][1]);
                mma_bf16(c[0], c[1], c[2], c[3], al[mi][0], al[mi][1], al[mi][2], al[mi][3], bhv[ni][0], bhv[ni][1]);
            }
    }

    float* Wh = W + (size_t)bh * Sdim * Sdim;
#pragma unroll
    for (int mi = 0; mi < 4; mi++) {
        const int r = q0 + wm + mi * 16 + ar;
#pragma unroll
        for (int ni = 0; ni < 4; ni++) {
            const int cc = k0 + wn + ni * 8 + ac;
            float* c = acc[mi][ni];
            *(float2*)&Wh[(size_t)r * Sdim + cc]       = make_float2(c[0], c[1]);
            *(float2*)&Wh[(size_t)(r + 8) * Sdim + cc] = make_float2(c[2], c[3]);
        }
    }
}

// ------------------- softmax -------------------
__global__ __launch_bounds__(256)
void softmax_kernel(float* __restrict__ W)
{
    float* p = W + (size_t)blockIdx.x * Sdim;
    const int tid = threadIdx.x, lane = tid & 31, warp = tid >> 5;

    float4 v0 = *(const float4*)(p + tid * 8);
    float4 v1 = *(const float4*)(p + tid * 8 + 4);
    float x[8] = {v0.x, v0.y, v0.z, v0.w, v1.x, v1.y, v1.z, v1.w};

    __shared__ float smax[8], ssum[8];

    float m = x[0];
#pragma unroll
    for (int j = 1; j < 8; j++) m = fmaxf(m, x[j]);
#pragma unroll
    for (int o = 16; o > 0; o >>= 1) m = fmaxf(m, __shfl_xor_sync(0xffffffffu, m, o));
    if (lane == 0) smax[warp] = m;
    __syncthreads();
    float bm = smax[0];
#pragma unroll
    for (int w = 1; w < 8; w++) bm = fmaxf(bm, smax[w]);

    float s = 0.f;
#pragma unroll
    for (int j = 0; j < 8; j++) { x[j] = __expf(x[j] - bm); s += x[j]; }
#pragma unroll
    for (int o = 16; o > 0; o >>= 1) s += __shfl_xor_sync(0xffffffffu, s, o);
    if (lane == 0) ssum[warp] = s;
    __syncthreads();
    float bs = 0.f;
#pragma unroll
    for (int w = 0; w < 8; w++) bs += ssum[w];

    const float inv = 1.f / bs;
#pragma unroll
    for (int j = 0; j < 8; j++) x[j] *= inv;
    *(float4*)(p + tid * 8)     = make_float4(x[0], x[1], x[2], x[3]);
    *(float4*)(p + tid * 8 + 4) = make_float4(x[4], x[5], x[6], x[7]);
}

// ------------------- PV HMMA kernel -------------------
// CTA: 128 q-rows x 128 d-cols, K=2048 in 64 chunks of 32, reg-prefetch pipeline.
#define LDB_PV 40
#define PV_SMEM (4 * 128 * LDB_PV * 2)   // 40960 B

__global__ __launch_bounds__(256, 1)
void pv_mma_kernel(const float* __restrict__ W, float* __restrict__ O)
{
    extern __shared__ __nv_bfloat16 sm[];
    __nv_bfloat16* sPhi = sm;
    __nv_bfloat16* sPlo = sm + 128 * LDB_PV;
    __nv_bfloat16* sVhi = sm + 2 * 128 * LDB_PV;
    __nv_bfloat16* sVlo = sm + 3 * 128 * LDB_PV;

    const int tid = threadIdx.x;
    const int q0 = blockIdx.x * 128;
    const int bh = blockIdx.y;

    const int row = tid >> 1, hf = tid & 1;
    const float* Wp = W + (size_t)bh * Sdim * Sdim + (size_t)(q0 + row) * Sdim + hf * 16;
    const __nv_bfloat16* Vhp = g_Vthi + (size_t)bh * Ddim * Sdim + (size_t)row * Sdim + hf * 16;
    const __nv_bfloat16* Vlp = g_Vtlo + (size_t)bh * Ddim * Sdim + (size_t)row * Sdim + hf * 16;

    const int lane = tid & 31, wid = tid >> 5;
    const int wm = (wid >> 2) * 64, wn = (wid & 3) * 32;
    const int ar = lane >> 2, ac = (lane & 3) * 2;

    float acc[4][4][4];
#pragma unroll
    for (int mi = 0; mi < 4; mi++)
#pragma unroll
        for (int ni = 0; ni < 4; ni++)
#pragma unroll
            for (int r = 0; r < 4; r++) acc[mi][ni][r] = 0.f;

    float4 fa[4];
    uint4 vbh[2], vbl[2];

    // prefetch chunk 0
#pragma unroll
    for (int g = 0; g < 4; g++) fa[g] = ((const float4*)Wp)[g];
#pragma unroll
    for (int u = 0; u < 2; u++) { vbh[u] = *(const uint4*)(Vhp + u * 8); vbl[u] = *(const uint4*)(Vlp + u * 8); }

    for (int c = 0; c < 64; c++) {
        __syncthreads();
        // store prefetched regs to smem (convert A to hi/lo)
        {
            const int sbase = row * LDB_PV + hf * 16;
#pragma unroll
            for (int g = 0; g < 4; g++) {
                uint32_t h0, h1, l0, l1;
                split2(fa[g].x, fa[g].y, h0, l0);
                split2(fa[g].z, fa[g].w, h1, l1);
                *(uint2*)&sPhi[sbase + g * 4] = make_uint2(h0, h1);
                *(uint2*)&sPlo[sbase + g * 4] = make_uint2(l0, l1);
            }
#pragma unroll
            for (int u = 0; u < 2; u++) {
                *(uint4*)&sVhi[sbase + u * 8] = vbh[u];
                *(uint4*)&sVlo[sbase + u * 8] = vbl[u];
            }
        }
        __syncthreads();

        if (c < 63) {
            const int off = (c + 1) * 32;
#pragma unroll
            for (int g = 0; g < 4; g++) fa[g] = ((const float4*)(Wp + off))[g];
#pragma unroll
            for (int u = 0; u < 2; u++) {
                vbh[u] = *(const uint4*)(Vhp + off + u * 8);
                vbl[u] = *(const uint4*)(Vlp + off + u * 8);
            }
        }

#pragma unroll
        for (int ks = 0; ks < 2; ks++) {
            const int kb = ks * 16;
            uint32_t ah[4][4], al[4][4], bhv[4][2], blv[4][2];
#pragma unroll
            for (int mi = 0; mi < 4; mi++) {
                const int r = wm + mi * 16 + ar;
                const __nv_bfloat16* ph = &sPhi[r * LDB_PV + kb + ac];
                const __nv_bfloat16* pl = &sPlo[r * LDB_PV + kb + ac];
                ah[mi][0] = ld32bf(ph);     ah[mi][1] = ld32bf(ph + 8 * LDB_PV);
                ah[mi][2] = ld32bf(ph + 8); ah[mi][3] = ld32bf(ph + 8 * LDB_PV + 8);
                al[mi][0] = ld32bf(pl);     al[mi][1] = ld32bf(pl + 8 * LDB_PV);
                al[mi][2] = ld32bf(pl + 8); al[mi][3] = ld32bf(pl + 8 * LDB_PV + 8);
            }
#pragma unroll
            for (int ni = 0; ni < 4; ni++) {
                const int n = wn + ni * 8 + ar;
                const __nv_bfloat16* ph = &sVhi[n * LDB_PV + kb + ac];
                const __nv_bfloat16* pl = &sVlo[n * LDB_PV + kb + ac];
                bhv[ni][0] = ld32bf(ph); bhv[ni][1] = ld32bf(ph + 8);
                blv[ni][0] = ld32bf(pl); blv[ni][1] = ld32bf(pl + 8);
            }
#pragma unroll
            for (int mi = 0; mi < 4; mi++)
#pragma unroll
                for (int ni = 0; ni < 4; ni++) {
                    float* cc = acc[mi][ni];
                    mma_bf16(cc[0], cc[1], cc[2], cc[3], ah[mi][0], ah[mi][1], ah[mi][2], ah[mi][3], bhv[ni][0], bhv[ni][1]);
                    mma_bf16(cc[0], cc[1], cc[2], cc[3], ah[mi][0], ah[mi][1], ah[mi][2], ah[mi][3], blv[ni][0], blv[ni][1]);
                    mma_bf16(cc[0], cc[1], cc[2], cc[3], al[mi][0], al[mi][1], al[mi][2], al[mi][3], bhv[ni][0], bhv[ni][1]);
                }
        }
    }

    float* Oh = O + (size_t)bh * Sdim * Ddim;
#pragma unroll
    for (int mi = 0; mi < 4; mi++) {
        const int r = q0 + wm + mi * 16 + ar;
#pragma unroll
        for (int ni = 0; ni < 4; ni++) {
            const int cc = wn + ni * 8 + ac;
            float* c = acc[mi][ni];
            *(float2*)&Oh[(size_t)r * Ddim + cc]       = make_float2(c[0], c[1]);
            *(float2*)&Oh[(size_t)(r + 8) * Ddim + cc] = make_float2(c[2], c[3]);
        }
    }
}

// ------------------- launch -------------------
extern "C" void kernel_launch(void* const* d_in, const int* in_sizes, int n_in,
                              void* d_out, int out_size)
{
    const float* Q = (const float*)d_in[0];
    const float* K = (const float*)d_in[1];
    const float* V = (const float*)d_in[2];
    float* out = (float*)d_out;
    float* Wt  = out + (size_t)NELEM;  // weights region

    cudaFuncSetAttribute(qk_mma_kernel, cudaFuncAttributeMaxDynamicSharedMemorySize, QK_SMEM);
    cudaFuncSetAttribute(pv_mma_kernel, cudaFuncAttributeMaxDynamicSharedMemorySize, PV_SMEM);

    conv_qk_kernel<<<2 * (NELEM / 4) / 256, 256>>>(Q, K);
    conv_v_kernel<<<dim3(Sdim / 32, Ddim / 32, BHdim), dim3(32, 8)>>>(V);

    qk_mma_kernel<<<dim3(Sdim / 128, Sdim / 128, BHdim), 256, QK_SMEM>>>(Wt);

    softmax_kernel<<<dim3(BHdim * Sdim), 256>>>(Wt);

    pv_mma_kernel<<<dim3(Sdim / 128, BHdim), 256, PV_SMEM>>>(Wt, out);
}